// round 4
// baseline (speedup 1.0000x reference)
#include <cuda_runtime.h>
#include <math.h>

#define NRAYS 131072
#define TPB 128

__global__ void __launch_bounds__(TPB) vr_serial(
    const float* __restrict__ ro, const float* __restrict__ rd,
    const float* __restrict__ Wd, const float* __restrict__ Wc,
    float* __restrict__ out)
{
    const int ray = blockIdx.x * TPB + threadIdx.x;
    if (ray >= NRAYS) return;

    float ta[64];     // coarse t values
    float wts[64];    // weights + 1e-5 for CDF
    float cdf[65];
    float ts[64];     // importance samples (generated sorted)
    float ft[128];    // merged fine t values

    // ---- per-ray dot products: pos@W = (ro.W) + t*(rd.W) ----
    const float ox = ro[3 * ray + 0], oy = ro[3 * ray + 1], oz = ro[3 * ray + 2];
    const float dx = rd[3 * ray + 0], dy = rd[3 * ray + 1], dz = rd[3 * ray + 2];
    const float wd0 = Wd[0], wd1 = Wd[1], wd2 = Wd[2];
    const float ad = ox * wd0 + oy * wd1 + oz * wd2;
    const float bd = dx * wd0 + dy * wd1 + dz * wd2;
    float ac[3], bc[3];
#pragma unroll
    for (int k = 0; k < 3; k++) {
        float w0 = Wc[k], w1 = Wc[3 + k], w2 = Wc[6 + k];  // Wc[j][k], row-major
        ac[k] = ox * w0 + oy * w1 + oz * w2;
        bc[k] = dx * w0 + dy * w1 + dz * w2;
    }

    // ================= COARSE PASS (sequential, exact) =================
    float trans = 1.0f;
    float sr = 0.f, sg = 0.f, sb = 0.f, sd = 0.f, sa = 0.f, wtotal = 0.f;
    for (int i = 0; i < 64; i++) {
        float x = (i == 63) ? 1.0f : (float)i * (1.0f / 63.0f);
        float t = 2.0f + 4.0f * x;
        ta[i] = t;
        float dist;
        if (i < 63) {
            float xn = (i == 62) ? 1.0f : (float)(i + 1) * (1.0f / 63.0f);
            dist = (2.0f + 4.0f * xn) - t;
        } else {
            dist = 1e10f;
        }
        float ld = ad + t * bd;
        float dens = fmaxf(ld, 0.0f) + log1pf(expf(-fabsf(ld)));  // softplus
        float a = 1.0f - expf(-dens * dist);
        float w = a * trans;
        trans = trans * ((1.0f - a) + 1e-10f);
        float cr = 1.0f / (1.0f + expf(-(ac[0] + t * bc[0])));
        float cg = 1.0f / (1.0f + expf(-(ac[1] + t * bc[1])));
        float cb = 1.0f / (1.0f + expf(-(ac[2] + t * bc[2])));
        sr += w * cr; sg += w * cg; sb += w * cb;
        sd += w * t;  sa += w;
        float wp = w + 1e-5f;
        wts[i] = wp;
        wtotal += wp;
    }

    // ---- CDF (normalize then cumsum, like reference) ----
    {
        float invW = 1.0f / wtotal;
        float c = 0.0f;
        cdf[0] = 0.0f;
        for (int i = 0; i < 64; i++) {
            c += wts[i] * invW;
            cdf[i + 1] = c;
        }
    }

    // ---- inverse-CDF sampling: searchsorted(cdf, u, 'right') via sweep ----
    {
        int idx = 0;
        for (int k = 0; k < 64; k++) {
            float u = (k == 63) ? 1.0f : (float)k * (1.0f / 63.0f);
            while (idx < 65 && cdf[idx] <= u) idx++;
            // idx = count of cdf entries <= u, in [1,65]
            int below = idx - 1;                 // in [0,64]
            int above = (idx < 64) ? idx : 64;
            float cdf0 = cdf[below];
            float cdf1 = cdf[above];
            float bin0 = ta[(below < 63) ? below : 63];
            float bin1 = ta[(above < 63) ? above : 63];
            float denom = cdf1 - cdf0;
            if (denom < 1e-5f) denom = 1.0f;
            float tt = (u - cdf0) / denom;
            ts[k] = bin0 + tt * (bin1 - bin0);
        }
    }

    // ---- merge two sorted length-64 arrays (== sort of concat) ----
    {
        int ia = 0, ib = 0;
        for (int j = 0; j < 128; j++) {
            bool take_a;
            if (ia >= 64) take_a = false;
            else if (ib >= 64) take_a = true;
            else take_a = (ta[ia] <= ts[ib]);
            ft[j] = take_a ? ta[ia++] : ts[ib++];
        }
    }

    // ================= FINE PASS (sequential, exact) =================
    float ftr = 1.0f;
    float fsr = 0.f, fsg = 0.f, fsb = 0.f, fsd = 0.f, fsa = 0.f;
    for (int i = 0; i < 128; i++) {
        float t = ft[i];
        float dist = (i < 127) ? (ft[i + 1] - t) : 1e10f;
        float ld = ad + t * bd;
        float dens = fmaxf(ld, 0.0f) + log1pf(expf(-fabsf(ld)));
        float a = 1.0f - expf(-dens * dist);
        float w = a * ftr;
        ftr = ftr * ((1.0f - a) + 1e-10f);
        float cr = 1.0f / (1.0f + expf(-(ac[0] + t * bc[0])));
        float cg = 1.0f / (1.0f + expf(-(ac[1] + t * bc[1])));
        float cb = 1.0f / (1.0f + expf(-(ac[2] + t * bc[2])));
        fsr += w * cr; fsg += w * cg; fsb += w * cb;
        fsd += w * t;  fsa += w;
    }

    // ---- outputs: rgb(3N), depth(N), acc(N), frgb(3N), fdepth(N), facc(N) ----
    const int N = NRAYS;
    float bgc = 1.0f - sa;
    out[3 * ray + 0] = sr + bgc;
    out[3 * ray + 1] = sg + bgc;
    out[3 * ray + 2] = sb + bgc;
    out[3 * N + ray] = sd;
    out[4 * N + ray] = sa;
    float fbgc = 1.0f - fsa;
    out[5 * N + 3 * ray + 0] = fsr + fbgc;
    out[5 * N + 3 * ray + 1] = fsg + fbgc;
    out[5 * N + 3 * ray + 2] = fsb + fbgc;
    out[8 * N + ray] = fsd;
    out[9 * N + ray] = fsa;
}

extern "C" void kernel_launch(void* const* d_in, const int* in_sizes, int n_in,
                              void* d_out, int out_size) {
    // Size-robust input binding: Wd has 3 elements, Wc has 9; the two
    // 3*NRAYS float arrays are ray_origins then ray_directions (in order).
    const float* ro = nullptr;
    const float* rd = nullptr;
    const float* Wd = nullptr;
    const float* Wc = nullptr;
    for (int i = 0; i < n_in; i++) {
        int s = in_sizes[i];
        if (s == 3) Wd = (const float*)d_in[i];
        else if (s == 9) Wc = (const float*)d_in[i];
        else if (s == 3 * NRAYS) {
            if (!ro) ro = (const float*)d_in[i];
            else if (!rd) rd = (const float*)d_in[i];
        }
    }
    vr_serial<<<(NRAYS + TPB - 1) / TPB, TPB>>>(ro, rd, Wd, Wc, (float*)d_out);
}

// round 7
// speedup vs baseline: 1.2309x; 1.2309x over previous
#include <cuda_runtime.h>

#define NRAYS 131072
#define TPB 128

__device__ __forceinline__ float t_of(int i) {
    float x = (i == 63) ? 1.0f : (float)i * (1.0f / 63.0f);
    return fmaf(4.0f, x, 2.0f);
}
__device__ __forceinline__ float rcp_approx(float x) {
    float y;
    asm("rcp.approx.f32 %0, %1;" : "=f"(y) : "f"(x));
    return y;
}
__device__ __forceinline__ float sigmoid_f(float x) {
    return rcp_approx(1.0f + __expf(-x));
}
// Accurate log1p(y) for y in [0,1]: series for small y (avoids 1+y==1
// catastrophic truncation that zeroed densities), __logf otherwise.
__device__ __forceinline__ float log1p_fast(float y) {
    if (y < 0.03125f) {
        // y*(1 - y/2 + y^2/3 - y^3/4), rel err ~2e-7 at y=2^-5
        return y * fmaf(y, fmaf(y, fmaf(-0.25f, y, 1.0f / 3.0f), -0.5f), 1.0f);
    }
    return __logf(1.0f + y);
}
__device__ __forceinline__ float softplus_f(float x) {
    return fmaxf(x, 0.0f) + log1p_fast(__expf(-fabsf(x)));
}

__global__ void __launch_bounds__(TPB) vr_stream(
    const float* __restrict__ ro, const float* __restrict__ rd,
    const float* __restrict__ Wd, const float* __restrict__ Wc,
    float* __restrict__ out)
{
    const int ray = blockIdx.x * TPB + threadIdx.x;
    if (ray >= NRAYS) return;

    float cdf[65];   // raw cumsum of (w + 1e-5); only local array

    // ---- per-ray dot products: pos@W = (ro.W) + t*(rd.W) ----
    const float ox = ro[3 * ray + 0], oy = ro[3 * ray + 1], oz = ro[3 * ray + 2];
    const float dx = rd[3 * ray + 0], dy = rd[3 * ray + 1], dz = rd[3 * ray + 2];
    const float wd0 = __ldg(&Wd[0]), wd1 = __ldg(&Wd[1]), wd2 = __ldg(&Wd[2]);
    const float ad = ox * wd0 + oy * wd1 + oz * wd2;
    const float bd = dx * wd0 + dy * wd1 + dz * wd2;
    float ac0, ac1, ac2, bc0, bc1, bc2;
    {
        float w0 = __ldg(&Wc[0]), w1 = __ldg(&Wc[3]), w2 = __ldg(&Wc[6]);
        ac0 = ox * w0 + oy * w1 + oz * w2; bc0 = dx * w0 + dy * w1 + dz * w2;
        w0 = __ldg(&Wc[1]); w1 = __ldg(&Wc[4]); w2 = __ldg(&Wc[7]);
        ac1 = ox * w0 + oy * w1 + oz * w2; bc1 = dx * w0 + dy * w1 + dz * w2;
        w0 = __ldg(&Wc[2]); w1 = __ldg(&Wc[5]); w2 = __ldg(&Wc[8]);
        ac2 = ox * w0 + oy * w1 + oz * w2; bc2 = dx * w0 + dy * w1 + dz * w2;
    }

    // ================= COARSE PASS (streaming) =================
    float trans = 1.0f;
    float sr = 0.f, sg = 0.f, sb = 0.f, sd = 0.f, sa = 0.f;
    float csum = 0.0f;
    cdf[0] = 0.0f;
    float t = 2.0f;  // t_of(0)
    for (int i = 0; i < 64; i++) {
        float tn = (i < 63) ? t_of(i + 1) : t;
        float dist = (i < 63) ? (tn - t) : 1e10f;
        float dens = softplus_f(fmaf(t, bd, ad));
        float a = 1.0f - __expf(-dens * dist);
        float w = a * trans;
        trans = trans * ((1.0f - a) + 1e-10f);
        float cr = sigmoid_f(fmaf(t, bc0, ac0));
        float cg = sigmoid_f(fmaf(t, bc1, ac1));
        float cb = sigmoid_f(fmaf(t, bc2, ac2));
        sr += w * cr; sg += w * cg; sb += w * cb;
        sd += w * t;  sa += w;
        csum += w + 1e-5f;
        cdf[i + 1] = csum;
        t = tn;
    }
    const float invW = 1.0f / csum;

    // ====== FUSED: inverse-CDF sampling + merge + FINE PASS ======
    int p = 1;                 // cdf[0]=0 <= u always
    int ia = 0, ib = 0;
    float tav = 2.0f;          // t_of(ia)

    auto gen_ts = [&](int k) -> float {
        float u = (k == 63) ? 1.0f : (float)k * (1.0f / 63.0f);
        while (p < 65 && cdf[p] * invW <= u) p++;
        int below = p - 1;
        int above = (p < 64) ? p : 64;
        float cdf0 = cdf[below] * invW;
        float cdf1 = cdf[above] * invW;
        float bin0 = t_of((below < 63) ? below : 63);
        float bin1 = t_of((above < 63) ? above : 63);
        float denom = cdf1 - cdf0;
        if (denom < 1e-5f) denom = 1.0f;
        float tt = (u - cdf0) / denom;
        return fmaf(tt, bin1 - bin0, bin0);
    };

    float tsv = gen_ts(0);

    auto next_val = [&]() -> float {
        bool takeA = (ia < 64) && (tav <= tsv);
        float v;
        if (takeA) {
            v = tav; ia++;
            tav = (ia < 64) ? t_of(ia) : 3.0e38f;
        } else {
            v = tsv; ib++;
            tsv = (ib < 64) ? gen_ts(ib) : 3.0e38f;
        }
        return v;
    };

    float cur = next_val();
    float ftr = 1.0f;
    float fsr = 0.f, fsg = 0.f, fsb = 0.f, fsd = 0.f, fsa = 0.f;
    for (int j = 0; j < 128; j++) {
        float nxt = 0.0f, dist;
        if (j < 127) { nxt = next_val(); dist = nxt - cur; }
        else dist = 1e10f;
        float dens = softplus_f(fmaf(cur, bd, ad));
        float a = 1.0f - __expf(-dens * dist);
        float w = a * ftr;
        ftr = ftr * ((1.0f - a) + 1e-10f);
        float cr = sigmoid_f(fmaf(cur, bc0, ac0));
        float cg = sigmoid_f(fmaf(cur, bc1, ac1));
        float cb = sigmoid_f(fmaf(cur, bc2, ac2));
        fsr += w * cr; fsg += w * cg; fsb += w * cb;
        fsd += w * cur; fsa += w;
        cur = nxt;
    }

    // ---- outputs: rgb(3N), depth(N), acc(N), frgb(3N), fdepth(N), facc(N) ----
    const int N = NRAYS;
    float bgc = 1.0f - sa;
    out[3 * ray + 0] = sr + bgc;
    out[3 * ray + 1] = sg + bgc;
    out[3 * ray + 2] = sb + bgc;
    out[3 * N + ray] = sd;
    out[4 * N + ray] = sa;
    float fbgc = 1.0f - fsa;
    out[5 * N + 3 * ray + 0] = fsr + fbgc;
    out[5 * N + 3 * ray + 1] = fsg + fbgc;
    out[5 * N + 3 * ray + 2] = fsb + fbgc;
    out[8 * N + ray] = fsd;
    out[9 * N + ray] = fsa;
}

extern "C" void kernel_launch(void* const* d_in, const int* in_sizes, int n_in,
                              void* d_out, int out_size) {
    const float* ro = nullptr;
    const float* rd = nullptr;
    const float* Wd = nullptr;
    const float* Wc = nullptr;
    for (int i = 0; i < n_in; i++) {
        int s = in_sizes[i];
        if (s == 3) Wd = (const float*)d_in[i];
        else if (s == 9) Wc = (const float*)d_in[i];
        else if (s == 3 * NRAYS) {
            if (!ro) ro = (const float*)d_in[i];
            else if (!rd) rd = (const float*)d_in[i];
        }
    }
    vr_stream<<<(NRAYS + TPB - 1) / TPB, TPB>>>(ro, rd, Wd, Wc, (float*)d_out);
}

// round 8
// speedup vs baseline: 1.8397x; 1.4946x over previous
#include <cuda_runtime.h>

#define NRAYS 131072
#define WPB 8            // warps (rays) per block
#define NS 64
#define NIMP 64
#define NF 128

__device__ __forceinline__ float rcp_approx(float x) {
    float y;
    asm("rcp.approx.f32 %0, %1;" : "=f"(y) : "f"(x));
    return y;
}
__device__ __forceinline__ float sigmoid_f(float x) {
    return rcp_approx(1.0f + __expf(-x));
}
// Accurate log1p(y) for y in [0,1]: series for small y (avoids the 1+y==1
// truncation that zeroed densities -> the 7.04e-2 bug), __logf otherwise.
__device__ __forceinline__ float log1p_fast(float y) {
    if (y < 0.03125f) {
        return y * fmaf(y, fmaf(y, fmaf(-0.25f, y, 1.0f / 3.0f), -0.5f), 1.0f);
    }
    return __logf(1.0f + y);
}
__device__ __forceinline__ float softplus_f(float x) {
    return fmaxf(x, 0.0f) + log1p_fast(__expf(-fabsf(x)));
}
__device__ __forceinline__ float warp_red_sum(float x) {
#pragma unroll
    for (int d = 16; d > 0; d >>= 1) x += __shfl_xor_sync(0xffffffffu, x, d);
    return x;
}
__device__ __forceinline__ float warp_scan_prod(float x, int lane) {
#pragma unroll
    for (int d = 1; d < 32; d <<= 1) {
        float v = __shfl_up_sync(0xffffffffu, x, d);
        if (lane >= d) x *= v;
    }
    return x;
}
__device__ __forceinline__ float warp_scan_sum(float x, int lane) {
#pragma unroll
    for (int d = 1; d < 32; d <<= 1) {
        float v = __shfl_up_sync(0xffffffffu, x, d);
        if (lane >= d) x += v;
    }
    return x;
}

// count of c[i] <= u over 65 entries (searchsorted side='right')
__device__ __forceinline__ int ub_cdf65(const float* c, float u) {
    int lo = 0, hi = 65;
#pragma unroll
    for (int it = 0; it < 7; it++) {
        if (lo < hi) {
            int mid = (lo + hi) >> 1;
            if (c[mid] <= u) lo = mid + 1; else hi = mid;
        }
    }
    return lo;
}
// count of a[i] < v over 64 entries (answer in [0,64] -> 7 guarded iters)
__device__ __forceinline__ int lb64(const float* a, float v) {
    int lo = 0, hi = 64;
#pragma unroll
    for (int it = 0; it < 7; it++) {
        if (lo < hi) {
            int mid = (lo + hi) >> 1;
            if (a[mid] < v) lo = mid + 1; else hi = mid;
        }
    }
    return lo;
}
// count of a[i] <= v over 64 entries
__device__ __forceinline__ int ub64(const float* a, float v) {
    int lo = 0, hi = 64;
#pragma unroll
    for (int it = 0; it < 7; it++) {
        if (lo < hi) {
            int mid = (lo + hi) >> 1;
            if (a[mid] <= v) lo = mid + 1; else hi = mid;
        }
    }
    return lo;
}

__global__ void __launch_bounds__(32 * WPB) vr_kernel(
    const float* __restrict__ ro, const float* __restrict__ rd,
    const float* __restrict__ Wd, const float* __restrict__ Wc,
    float* __restrict__ out)
{
    const int w = threadIdx.x >> 5;
    const int lane = threadIdx.x & 31;
    const int ray = blockIdx.x * WPB + w;

    __shared__ float s_ta[WPB][NS];
    __shared__ float s_ts[WPB][NIMP];
    __shared__ float s_cdf[WPB][NS + 1];
    __shared__ float s_ft[WPB][NF + 1];

    float* ta = s_ta[w];
    float* ts = s_ts[w];
    float* cdf = s_cdf[w];
    float* ft = s_ft[w];

    // ---- per-ray precompute: pos @ W = (ro.W) + t*(rd.W) ----
    const float ox = ro[3 * ray + 0], oy = ro[3 * ray + 1], oz = ro[3 * ray + 2];
    const float dx = rd[3 * ray + 0], dy = rd[3 * ray + 1], dz = rd[3 * ray + 2];
    const float wd0 = __ldg(&Wd[0]), wd1 = __ldg(&Wd[1]), wd2 = __ldg(&Wd[2]);
    const float ad = ox * wd0 + oy * wd1 + oz * wd2;
    const float bd = dx * wd0 + dy * wd1 + dz * wd2;
    float ac[3], bc[3];
#pragma unroll
    for (int k = 0; k < 3; k++) {
        float w0 = __ldg(&Wc[k]), w1 = __ldg(&Wc[3 + k]), w2 = __ldg(&Wc[6 + k]);
        ac[k] = ox * w0 + oy * w1 + oz * w2;
        bc[k] = dx * w0 + dy * w1 + dz * w2;
    }

    // ================= COARSE PASS (2 samples/lane) =================
    float t_c[2], al_c[2], f_c[2], cr_c[2], cg_c[2], cb_c[2];
#pragma unroll
    for (int c = 0; c < 2; c++) {
        int i = 2 * lane + c;
        float x = (i == 63) ? 1.0f : (float)i * (1.0f / 63.0f);
        float t = fmaf(4.0f, x, 2.0f);
        ta[i] = t;
        float dist;
        if (i < 63) {
            float xn = (i == 62) ? 1.0f : (float)(i + 1) * (1.0f / 63.0f);
            dist = fmaf(4.0f, xn, 2.0f) - t;
        } else {
            dist = 1e10f;
        }
        float dens = softplus_f(fmaf(t, bd, ad));
        float a = 1.0f - __expf(-dens * dist);
        al_c[c] = a;
        f_c[c] = (1.0f - a) + 1e-10f;
        t_c[c] = t;
        cr_c[c] = sigmoid_f(fmaf(t, bc[0], ac[0]));
        cg_c[c] = sigmoid_f(fmaf(t, bc[1], ac[1]));
        cb_c[c] = sigmoid_f(fmaf(t, bc[2], ac[2]));
    }
    // exclusive product scan of transmittance factors over 64 (2 per lane)
    float P = f_c[0] * f_c[1];
    float S = warp_scan_prod(P, lane);
    float E = __shfl_up_sync(0xffffffffu, S, 1);
    if (lane == 0) E = 1.0f;

    float wgt_c[2];
    wgt_c[0] = al_c[0] * E;
    wgt_c[1] = al_c[1] * (E * f_c[0]);

    float sr = wgt_c[0] * cr_c[0] + wgt_c[1] * cr_c[1];
    float sg = wgt_c[0] * cg_c[0] + wgt_c[1] * cg_c[1];
    float sb = wgt_c[0] * cb_c[0] + wgt_c[1] * cb_c[1];
    float sd = wgt_c[0] * t_c[0] + wgt_c[1] * t_c[1];
    float sa = wgt_c[0] + wgt_c[1];
    sr = warp_red_sum(sr); sg = warp_red_sum(sg); sb = warp_red_sum(sb);
    sd = warp_red_sum(sd); sa = warp_red_sum(sa);

    // ---- CDF ----
    float wp0 = wgt_c[0] + 1e-5f;
    float wp1 = wgt_c[1] + 1e-5f;
    float Ps = wp0 + wp1;
    float Ss = warp_scan_sum(Ps, lane);
    float Es = __shfl_up_sync(0xffffffffu, Ss, 1);
    if (lane == 0) Es = 0.0f;
    float total = __shfl_sync(0xffffffffu, Ss, 31);
    float inv_total = 1.0f / total;
    if (lane == 0) cdf[0] = 0.0f;
    cdf[2 * lane + 1] = (Es + wp0) * inv_total;
    cdf[2 * lane + 2] = (Es + Ps) * inv_total;
    __syncwarp();

    // ---- inverse-CDF importance sampling (2 u's / lane) ----
#pragma unroll
    for (int c = 0; c < 2; c++) {
        int k = 2 * lane + c;
        float u = (k == 63) ? 1.0f : (float)k * (1.0f / 63.0f);
        int idx = ub_cdf65(cdf, u);     // in [1,65]
        int below = idx - 1;
        int above = (idx < 64) ? idx : 64;
        float cdf0 = cdf[below];
        float cdf1 = cdf[above];
        float bin0 = ta[(below < 63) ? below : 63];
        float bin1 = ta[(above < 63) ? above : 63];
        float denom = cdf1 - cdf0;
        if (denom < 1e-5f) denom = 1.0f;
        float tt = (u - cdf0) / denom;
        ts[k] = fmaf(tt, bin1 - bin0, bin0);
    }
    __syncwarp();

    // ---- merge two sorted length-64 arrays into ft[128] ----
#pragma unroll
    for (int c = 0; c < 2; c++) {
        int j = 2 * lane + c;
        float av = ta[j];
        ft[j + lb64(ts, av)] = av;       // a before equal b
        float bv = ts[j];
        ft[j + ub64(ta, bv)] = bv;
    }
    __syncwarp();

    // ================= FINE PASS (4 samples/lane) =================
    float tf[4], al[4], ff[4], fr[4], fg[4], fb[4];
#pragma unroll
    for (int c = 0; c < 4; c++) {
        int i = 4 * lane + c;
        float t = ft[i];
        float dist = (i < 127) ? (ft[i + 1] - t) : 1e10f;
        float dens = softplus_f(fmaf(t, bd, ad));
        float a = 1.0f - __expf(-dens * dist);
        al[c] = a;
        ff[c] = (1.0f - a) + 1e-10f;
        tf[c] = t;
        fr[c] = sigmoid_f(fmaf(t, bc[0], ac[0]));
        fg[c] = sigmoid_f(fmaf(t, bc[1], ac[1]));
        fb[c] = sigmoid_f(fmaf(t, bc[2], ac[2]));
    }
    float Pf = (ff[0] * ff[1]) * (ff[2] * ff[3]);
    float Sf = warp_scan_prod(Pf, lane);
    float Ef = __shfl_up_sync(0xffffffffu, Sf, 1);
    if (lane == 0) Ef = 1.0f;

    float fsr = 0.f, fsg = 0.f, fsb = 0.f, fsd = 0.f, fsa = 0.f;
    float trans = Ef;
#pragma unroll
    for (int c = 0; c < 4; c++) {
        float wgt = al[c] * trans;
        fsr += wgt * fr[c];
        fsg += wgt * fg[c];
        fsb += wgt * fb[c];
        fsd += wgt * tf[c];
        fsa += wgt;
        trans *= ff[c];
    }
    fsr = warp_red_sum(fsr); fsg = warp_red_sum(fsg); fsb = warp_red_sum(fsb);
    fsd = warp_red_sum(fsd); fsa = warp_red_sum(fsa);

    // ---- outputs: rgb(3N), depth(N), acc(N), frgb(3N), fdepth(N), facc(N) ----
    if (lane == 0) {
        const int N = NRAYS;
        float bgc = 1.0f - sa;
        out[3 * ray + 0] = sr + bgc;
        out[3 * ray + 1] = sg + bgc;
        out[3 * ray + 2] = sb + bgc;
        out[3 * N + ray] = sd;
        out[4 * N + ray] = sa;
        float fbgc = 1.0f - fsa;
        out[5 * N + 3 * ray + 0] = fsr + fbgc;
        out[5 * N + 3 * ray + 1] = fsg + fbgc;
        out[5 * N + 3 * ray + 2] = fsb + fbgc;
        out[8 * N + ray] = fsd;
        out[9 * N + ray] = fsa;
    }
}

extern "C" void kernel_launch(void* const* d_in, const int* in_sizes, int n_in,
                              void* d_out, int out_size) {
    const float* ro = nullptr;
    const float* rd = nullptr;
    const float* Wd = nullptr;
    const float* Wc = nullptr;
    for (int i = 0; i < n_in; i++) {
        int s = in_sizes[i];
        if (s == 3) Wd = (const float*)d_in[i];
        else if (s == 9) Wc = (const float*)d_in[i];
        else if (s == 3 * NRAYS) {
            if (!ro) ro = (const float*)d_in[i];
            else if (!rd) rd = (const float*)d_in[i];
        }
    }
    vr_kernel<<<NRAYS / WPB, 32 * WPB>>>(ro, rd, Wd, Wc, (float*)d_out);
}

// round 9
// speedup vs baseline: 2.1137x; 1.1490x over previous
#include <cuda_runtime.h>

#define NRAYS 131072
#define WPB 8            // warps (rays) per block
#define NS 64
#define NF 128

__device__ __forceinline__ float rcp_approx(float x) {
    float y;
    asm("rcp.approx.f32 %0, %1;" : "=f"(y) : "f"(x));
    return y;
}
__device__ __forceinline__ float sigmoid_f(float x) {
    return rcp_approx(1.0f + __expf(-x));
}
// Accurate log1p(y) for y in [0,1]: series for small y (avoids the 1+y==1
// truncation that zeroed densities), __logf otherwise.
__device__ __forceinline__ float log1p_fast(float y) {
    if (y < 0.03125f) {
        return y * fmaf(y, fmaf(y, fmaf(-0.25f, y, 1.0f / 3.0f), -0.5f), 1.0f);
    }
    return __logf(1.0f + y);
}
__device__ __forceinline__ float softplus_f(float x) {
    return fmaxf(x, 0.0f) + log1p_fast(__expf(-fabsf(x)));
}
// coarse grid value, exact same floats as the coarse pass computes
__device__ __forceinline__ float t_of_i(int i) {
    float x = (i == 63) ? 1.0f : (float)i * (1.0f / 63.0f);
    return fmaf(4.0f, x, 2.0f);
}
__device__ __forceinline__ float warp_red_sum(float x) {
#pragma unroll
    for (int d = 16; d > 0; d >>= 1) x += __shfl_xor_sync(0xffffffffu, x, d);
    return x;
}
__device__ __forceinline__ float warp_scan_prod(float x, int lane) {
#pragma unroll
    for (int d = 1; d < 32; d <<= 1) {
        float v = __shfl_up_sync(0xffffffffu, x, d);
        if (lane >= d) x *= v;
    }
    return x;
}
__device__ __forceinline__ float warp_scan_sum(float x, int lane) {
#pragma unroll
    for (int d = 1; d < 32; d <<= 1) {
        float v = __shfl_up_sync(0xffffffffu, x, d);
        if (lane >= d) x += v;
    }
    return x;
}

// count of c[i] <= u over exactly 64 sorted entries (result in [0,64])
__device__ __forceinline__ int cnt64_le(const float* c, float u) {
    if (c[63] <= u) return 64;
    int pos = 0;
#pragma unroll
    for (int step = 32; step >= 1; step >>= 1)
        if (c[pos + step - 1] <= u) pos += step;
    return pos;
}
// count of c[i] < v over exactly 64 sorted entries (result in [0,64])
__device__ __forceinline__ int cnt64_lt(const float* c, float v) {
    if (c[63] < v) return 64;
    int pos = 0;
#pragma unroll
    for (int step = 32; step >= 1; step >>= 1)
        if (c[pos + step - 1] < v) pos += step;
    return pos;
}
// count of {i in [0,64): t_of_i(i) <= v}  -- analytic guess + exact correction
__device__ __forceinline__ int cnt_ta_le(float v) {
    float g = fmaf(v, 15.75f, -31.5f);     // (v-2)*63/4
    int c = (int)floorf(g) + 1;
    c = min(64, max(0, c));
    if (c < 64 && t_of_i(c) <= v) c++;
    if (c < 64 && t_of_i(c) <= v) c++;
    if (c > 0 && t_of_i(c - 1) > v) c--;
    if (c > 0 && t_of_i(c - 1) > v) c--;
    return c;
}

__global__ void __launch_bounds__(32 * WPB) vr_kernel(
    const float* __restrict__ ro, const float* __restrict__ rd,
    const float* __restrict__ Wd, const float* __restrict__ Wc,
    float* __restrict__ out)
{
    const int w = threadIdx.x >> 5;
    const int lane = threadIdx.x & 31;
    const int ray = blockIdx.x * WPB + w;

    __shared__ float s_ts[WPB][NS];              // importance samples
    __shared__ float s_cdf[WPB][NS + 1];         // normalized cdf
    __shared__ __align__(16) float s_ft[WPB][132]; // merged fine t (row 16B-aligned)

    float* ts = s_ts[w];
    float* cdf = s_cdf[w];
    float* ft = s_ft[w];

    // ---- per-ray precompute: pos @ W = (ro.W) + t*(rd.W) ----
    const float ox = ro[3 * ray + 0], oy = ro[3 * ray + 1], oz = ro[3 * ray + 2];
    const float dx = rd[3 * ray + 0], dy = rd[3 * ray + 1], dz = rd[3 * ray + 2];
    const float wd0 = __ldg(&Wd[0]), wd1 = __ldg(&Wd[1]), wd2 = __ldg(&Wd[2]);
    const float ad = ox * wd0 + oy * wd1 + oz * wd2;
    const float bd = dx * wd0 + dy * wd1 + dz * wd2;
    float ac[3], bc[3];
#pragma unroll
    for (int k = 0; k < 3; k++) {
        float w0 = __ldg(&Wc[k]), w1 = __ldg(&Wc[3 + k]), w2 = __ldg(&Wc[6 + k]);
        ac[k] = ox * w0 + oy * w1 + oz * w2;
        bc[k] = dx * w0 + dy * w1 + dz * w2;
    }

    // ================= COARSE PASS (2 samples/lane) =================
    float t_c[2], al_c[2], f_c[2], cr_c[2], cg_c[2], cb_c[2];
#pragma unroll
    for (int c = 0; c < 2; c++) {
        int i = 2 * lane + c;
        float t = t_of_i(i);
        float dist = (i < 63) ? (t_of_i(i + 1) - t) : 1e10f;
        float dens = softplus_f(fmaf(t, bd, ad));
        float a = 1.0f - __expf(-dens * dist);
        al_c[c] = a;
        f_c[c] = (1.0f - a) + 1e-10f;
        t_c[c] = t;
        cr_c[c] = sigmoid_f(fmaf(t, bc[0], ac[0]));
        cg_c[c] = sigmoid_f(fmaf(t, bc[1], ac[1]));
        cb_c[c] = sigmoid_f(fmaf(t, bc[2], ac[2]));
    }
    // exclusive product scan of transmittance factors over 64 (2 per lane)
    float P = f_c[0] * f_c[1];
    float S = warp_scan_prod(P, lane);
    float E = __shfl_up_sync(0xffffffffu, S, 1);
    if (lane == 0) E = 1.0f;

    float wgt0 = al_c[0] * E;
    float wgt1 = al_c[1] * (E * f_c[0]);

    float sr = wgt0 * cr_c[0] + wgt1 * cr_c[1];
    float sg = wgt0 * cg_c[0] + wgt1 * cg_c[1];
    float sb = wgt0 * cb_c[0] + wgt1 * cb_c[1];
    float sd = wgt0 * t_c[0] + wgt1 * t_c[1];
    float sa = wgt0 + wgt1;
    sr = warp_red_sum(sr); sg = warp_red_sum(sg); sb = warp_red_sum(sb);
    sd = warp_red_sum(sd); sa = warp_red_sum(sa);

    // ---- CDF ----
    float wp0 = wgt0 + 1e-5f;
    float wp1 = wgt1 + 1e-5f;
    float Ps = wp0 + wp1;
    float Ss = warp_scan_sum(Ps, lane);
    float Es = __shfl_up_sync(0xffffffffu, Ss, 1);
    if (lane == 0) Es = 0.0f;
    float total = __shfl_sync(0xffffffffu, Ss, 31);
    float inv_total = 1.0f / total;
    if (lane == 0) cdf[0] = 0.0f;
    cdf[2 * lane + 1] = (Es + wp0) * inv_total;
    cdf[2 * lane + 2] = (Es + Ps) * inv_total;
    __syncwarp();

    // ---- inverse-CDF importance sampling (2 u's / lane), values kept in regs ----
    float tsv[2];
#pragma unroll
    for (int c = 0; c < 2; c++) {
        int k = 2 * lane + c;
        float u = (k == 63) ? 1.0f : (float)k * (1.0f / 63.0f);
        int idx = 1 + cnt64_le(cdf + 1, u);   // searchsorted 'right' over 65 entries
        int below = idx - 1;
        int above = (idx < 64) ? idx : 64;
        float cdf0 = cdf[below];
        float cdf1 = cdf[above];
        float bin0 = t_of_i((below < 63) ? below : 63);
        float bin1 = t_of_i((above < 63) ? above : 63);
        float denom = cdf1 - cdf0;
        if (denom < 1e-5f) denom = 1.0f;
        float tt = (u - cdf0) / denom;
        float v = fmaf(tt, bin1 - bin0, bin0);
        tsv[c] = v;
        ts[k] = v;
    }
    __syncwarp();

    // ---- merge ranks: A (coarse, analytic) + B (importance) -> scatter to ft ----
#pragma unroll
    for (int c = 0; c < 2; c++) {
        int j = 2 * lane + c;
        float av = t_c[c];
        ft[j + cnt64_lt(ts, av)] = av;      // a before equal b
        float bv = tsv[c];
        ft[j + cnt_ta_le(bv)] = bv;
    }
    __syncwarp();

    // ================= FINE PASS (4 samples/lane, vectorized load) =================
    const float4 q = *reinterpret_cast<const float4*>(&ft[4 * lane]);
    const float t5 = ft[4 * lane + 4];       // lane 31: unused garbage (guarded)
    float tf[5] = {q.x, q.y, q.z, q.w, t5};

    float al[4], ff[4], fr[4], fg[4], fb[4];
#pragma unroll
    for (int c = 0; c < 4; c++) {
        int i = 4 * lane + c;
        float t = tf[c];
        float dist = (i < 127) ? (tf[c + 1] - t) : 1e10f;
        float dens = softplus_f(fmaf(t, bd, ad));
        float a = 1.0f - __expf(-dens * dist);
        al[c] = a;
        ff[c] = (1.0f - a) + 1e-10f;
        fr[c] = sigmoid_f(fmaf(t, bc[0], ac[0]));
        fg[c] = sigmoid_f(fmaf(t, bc[1], ac[1]));
        fb[c] = sigmoid_f(fmaf(t, bc[2], ac[2]));
    }
    float Pf = (ff[0] * ff[1]) * (ff[2] * ff[3]);
    float Sf = warp_scan_prod(Pf, lane);
    float Ef = __shfl_up_sync(0xffffffffu, Sf, 1);
    if (lane == 0) Ef = 1.0f;

    float fsr = 0.f, fsg = 0.f, fsb = 0.f, fsd = 0.f, fsa = 0.f;
    float trans = Ef;
#pragma unroll
    for (int c = 0; c < 4; c++) {
        float wgt = al[c] * trans;
        fsr += wgt * fr[c];
        fsg += wgt * fg[c];
        fsb += wgt * fb[c];
        fsd += wgt * tf[c];
        fsa += wgt;
        trans *= ff[c];
    }
    fsr = warp_red_sum(fsr); fsg = warp_red_sum(fsg); fsb = warp_red_sum(fsb);
    fsd = warp_red_sum(fsd); fsa = warp_red_sum(fsa);

    // ---- outputs: rgb(3N), depth(N), acc(N), frgb(3N), fdepth(N), facc(N) ----
    if (lane == 0) {
        const int N = NRAYS;
        float bgc = 1.0f - sa;
        out[3 * ray + 0] = sr + bgc;
        out[3 * ray + 1] = sg + bgc;
        out[3 * ray + 2] = sb + bgc;
        out[3 * N + ray] = sd;
        out[4 * N + ray] = sa;
        float fbgc = 1.0f - fsa;
        out[5 * N + 3 * ray + 0] = fsr + fbgc;
        out[5 * N + 3 * ray + 1] = fsg + fbgc;
        out[5 * N + 3 * ray + 2] = fsb + fbgc;
        out[8 * N + ray] = fsd;
        out[9 * N + ray] = fsa;
    }
}

extern "C" void kernel_launch(void* const* d_in, const int* in_sizes, int n_in,
                              void* d_out, int out_size) {
    const float* ro = nullptr;
    const float* rd = nullptr;
    const float* Wd = nullptr;
    const float* Wc = nullptr;
    for (int i = 0; i < n_in; i++) {
        int s = in_sizes[i];
        if (s == 3) Wd = (const float*)d_in[i];
        else if (s == 9) Wc = (const float*)d_in[i];
        else if (s == 3 * NRAYS) {
            if (!ro) ro = (const float*)d_in[i];
            else if (!rd) rd = (const float*)d_in[i];
        }
    }
    vr_kernel<<<NRAYS / WPB, 32 * WPB>>>(ro, rd, Wd, Wc, (float*)d_out);
}

// round 10
// speedup vs baseline: 2.3892x; 1.1303x over previous
#include <cuda_runtime.h>

#define NRAYS 131072
#define WPB 8            // warps (rays) per block
#define NS 64
#define NF 128

__device__ __forceinline__ float tanh_approx(float x) {
    float y;
    asm("tanh.approx.f32 %0, %1;" : "=f"(y) : "f"(x));
    return y;
}
// sigmoid(2*xh) = 0.5*tanh(xh)+0.5 ; caller passes the pre-halved logit
__device__ __forceinline__ float sigmoid_h(float xh) {
    return fmaf(0.5f, tanh_approx(xh), 0.5f);
}
// Accurate log1p(y) for y in [0,1]: series for small y (avoids the 1+y==1
// truncation that zeroed densities), __logf otherwise.
__device__ __forceinline__ float log1p_fast(float y) {
    if (y < 0.03125f) {
        return y * fmaf(y, fmaf(y, fmaf(-0.25f, y, 1.0f / 3.0f), -0.5f), 1.0f);
    }
    return __logf(1.0f + y);
}
__device__ __forceinline__ float softplus_f(float x) {
    return fmaxf(x, 0.0f) + log1p_fast(__expf(-fabsf(x)));
}
// coarse grid value, exact same floats as the coarse pass computes
__device__ __forceinline__ float t_of_i(int i) {
    float x = (i == 63) ? 1.0f : (float)i * (1.0f / 63.0f);
    return fmaf(4.0f, x, 2.0f);
}
__device__ __forceinline__ float warp_red_sum(float x) {
#pragma unroll
    for (int d = 16; d > 0; d >>= 1) x += __shfl_xor_sync(0xffffffffu, x, d);
    return x;
}
__device__ __forceinline__ float warp_scan_prod(float x, int lane) {
#pragma unroll
    for (int d = 1; d < 32; d <<= 1) {
        float v = __shfl_up_sync(0xffffffffu, x, d);
        if (lane >= d) x *= v;
    }
    return x;
}
__device__ __forceinline__ float warp_scan_sum(float x, int lane) {
#pragma unroll
    for (int d = 1; d < 32; d <<= 1) {
        float v = __shfl_up_sync(0xffffffffu, x, d);
        if (lane >= d) x += v;
    }
    return x;
}

// count of c[i] <= u over exactly 64 sorted entries (result in [0,64])
__device__ __forceinline__ int cnt64_le(const float* c, float u) {
    if (c[63] <= u) return 64;
    int pos = 0;
#pragma unroll
    for (int step = 32; step >= 1; step >>= 1)
        if (c[pos + step - 1] <= u) pos += step;
    return pos;
}
// count of c[i] < v over exactly 64 sorted entries (result in [0,64])
__device__ __forceinline__ int cnt64_lt(const float* c, float v) {
    if (c[63] < v) return 64;
    int pos = 0;
#pragma unroll
    for (int step = 32; step >= 1; step >>= 1)
        if (c[pos + step - 1] < v) pos += step;
    return pos;
}
// count of {i in [0,64): t_of_i(i) <= v}  -- analytic guess + exact correction
__device__ __forceinline__ int cnt_ta_le(float v) {
    float g = fmaf(v, 15.75f, -31.5f);     // (v-2)*63/4
    int c = (int)floorf(g) + 1;
    c = min(64, max(0, c));
    if (c < 64 && t_of_i(c) <= v) c++;
    if (c < 64 && t_of_i(c) <= v) c++;
    if (c > 0 && t_of_i(c - 1) > v) c--;
    if (c > 0 && t_of_i(c - 1) > v) c--;
    return c;
}

__global__ void __launch_bounds__(32 * WPB, 7) vr_kernel(
    const float* __restrict__ ro, const float* __restrict__ rd,
    const float* __restrict__ Wd, const float* __restrict__ Wc,
    float* __restrict__ out)
{
    const int w = threadIdx.x >> 5;
    const int lane = threadIdx.x & 31;
    const int ray = blockIdx.x * WPB + w;

    __shared__ float s_ts[WPB][NS];              // importance samples
    __shared__ float s_cdf[WPB][NS + 1];         // normalized cdf
    __shared__ __align__(16) float s_ft[WPB][132]; // merged fine t (row 16B-aligned)

    float* ts = s_ts[w];
    float* cdf = s_cdf[w];
    float* ft = s_ft[w];

    // ---- per-ray precompute: pos @ W = (ro.W) + t*(rd.W) ----
    const float ox = ro[3 * ray + 0], oy = ro[3 * ray + 1], oz = ro[3 * ray + 2];
    const float dx = rd[3 * ray + 0], dy = rd[3 * ray + 1], dz = rd[3 * ray + 2];
    const float wd0 = __ldg(&Wd[0]), wd1 = __ldg(&Wd[1]), wd2 = __ldg(&Wd[2]);
    const float ad = ox * wd0 + oy * wd1 + oz * wd2;
    const float bd = dx * wd0 + dy * wd1 + dz * wd2;
    float ach[3], bch[3];   // PRE-HALVED color coefficients for tanh-sigmoid
#pragma unroll
    for (int k = 0; k < 3; k++) {
        float w0 = __ldg(&Wc[k]), w1 = __ldg(&Wc[3 + k]), w2 = __ldg(&Wc[6 + k]);
        ach[k] = 0.5f * (ox * w0 + oy * w1 + oz * w2);
        bch[k] = 0.5f * (dx * w0 + dy * w1 + dz * w2);
    }

    // ================= COARSE PASS (2 samples/lane) =================
    float t_c[2], al_c[2], f_c[2], cr_c[2], cg_c[2], cb_c[2];
#pragma unroll
    for (int c = 0; c < 2; c++) {
        int i = 2 * lane + c;
        float t = t_of_i(i);
        float dist = (i < 63) ? (t_of_i(i + 1) - t) : 1e10f;
        float dens = softplus_f(fmaf(t, bd, ad));
        float a = 1.0f - __expf(-dens * dist);
        al_c[c] = a;
        f_c[c] = (1.0f - a) + 1e-10f;
        t_c[c] = t;
        cr_c[c] = sigmoid_h(fmaf(t, bch[0], ach[0]));
        cg_c[c] = sigmoid_h(fmaf(t, bch[1], ach[1]));
        cb_c[c] = sigmoid_h(fmaf(t, bch[2], ach[2]));
    }
    // exclusive product scan of transmittance factors over 64 (2 per lane)
    float P = f_c[0] * f_c[1];
    float S = warp_scan_prod(P, lane);
    float E = __shfl_up_sync(0xffffffffu, S, 1);
    if (lane == 0) E = 1.0f;

    float wgt0 = al_c[0] * E;
    float wgt1 = al_c[1] * (E * f_c[0]);

    float sr = wgt0 * cr_c[0] + wgt1 * cr_c[1];
    float sg = wgt0 * cg_c[0] + wgt1 * cg_c[1];
    float sb = wgt0 * cb_c[0] + wgt1 * cb_c[1];
    float sd = wgt0 * t_c[0] + wgt1 * t_c[1];
    float sa = wgt0 + wgt1;
    sr = warp_red_sum(sr); sg = warp_red_sum(sg); sb = warp_red_sum(sb);
    sd = warp_red_sum(sd); sa = warp_red_sum(sa);

    // ---- CDF ----
    float wp0 = wgt0 + 1e-5f;
    float wp1 = wgt1 + 1e-5f;
    float Ps = wp0 + wp1;
    float Ss = warp_scan_sum(Ps, lane);
    float Es = __shfl_up_sync(0xffffffffu, Ss, 1);
    if (lane == 0) Es = 0.0f;
    float total = __shfl_sync(0xffffffffu, Ss, 31);
    float inv_total = 1.0f / total;
    if (lane == 0) cdf[0] = 0.0f;
    cdf[2 * lane + 1] = (Es + wp0) * inv_total;
    cdf[2 * lane + 2] = (Es + Ps) * inv_total;
    __syncwarp();

    // ---- inverse-CDF importance sampling (2 u's / lane), values kept in regs ----
    float tsv[2];
#pragma unroll
    for (int c = 0; c < 2; c++) {
        int k = 2 * lane + c;
        float u = (k == 63) ? 1.0f : (float)k * (1.0f / 63.0f);
        int idx = 1 + cnt64_le(cdf + 1, u);   // searchsorted 'right' over 65 entries
        int below = idx - 1;
        int above = (idx < 64) ? idx : 64;
        float cdf0 = cdf[below];
        float cdf1 = cdf[above];
        float bin0 = t_of_i((below < 63) ? below : 63);
        float bin1 = t_of_i((above < 63) ? above : 63);
        float denom = cdf1 - cdf0;
        if (denom < 1e-5f) denom = 1.0f;
        float tt = (u - cdf0) / denom;
        float v = fmaf(tt, bin1 - bin0, bin0);
        tsv[c] = v;
        ts[k] = v;
    }
    __syncwarp();

    // ---- merge ranks: A (coarse, analytic) + B (importance) -> scatter to ft ----
#pragma unroll
    for (int c = 0; c < 2; c++) {
        int j = 2 * lane + c;
        float av = t_c[c];
        ft[j + cnt64_lt(ts, av)] = av;      // a before equal b
        float bv = tsv[c];
        ft[j + cnt_ta_le(bv)] = bv;
    }
    __syncwarp();

    // ================= FINE PASS (4 samples/lane, vectorized load) =================
    const float4 q = *reinterpret_cast<const float4*>(&ft[4 * lane]);
    const float t5 = ft[4 * lane + 4];       // lane 31: unused garbage (guarded)
    float tf[5] = {q.x, q.y, q.z, q.w, t5};

    float al[4], ff[4], fr[4], fg[4], fb[4];
#pragma unroll
    for (int c = 0; c < 4; c++) {
        int i = 4 * lane + c;
        float t = tf[c];
        float dist = (i < 127) ? (tf[c + 1] - t) : 1e10f;
        float dens = softplus_f(fmaf(t, bd, ad));
        float a = 1.0f - __expf(-dens * dist);
        al[c] = a;
        ff[c] = (1.0f - a) + 1e-10f;
        fr[c] = sigmoid_h(fmaf(t, bch[0], ach[0]));
        fg[c] = sigmoid_h(fmaf(t, bch[1], ach[1]));
        fb[c] = sigmoid_h(fmaf(t, bch[2], ach[2]));
    }
    float Pf = (ff[0] * ff[1]) * (ff[2] * ff[3]);
    float Sf = warp_scan_prod(Pf, lane);
    float Ef = __shfl_up_sync(0xffffffffu, Sf, 1);
    if (lane == 0) Ef = 1.0f;

    float fsr = 0.f, fsg = 0.f, fsb = 0.f, fsd = 0.f, fsa = 0.f;
    float trans = Ef;
#pragma unroll
    for (int c = 0; c < 4; c++) {
        float wgt = al[c] * trans;
        fsr += wgt * fr[c];
        fsg += wgt * fg[c];
        fsb += wgt * fb[c];
        fsd += wgt * tf[c];
        fsa += wgt;
        trans *= ff[c];
    }
    fsr = warp_red_sum(fsr); fsg = warp_red_sum(fsg); fsb = warp_red_sum(fsb);
    fsd = warp_red_sum(fsd); fsa = warp_red_sum(fsa);

    // ---- outputs: rgb(3N), depth(N), acc(N), frgb(3N), fdepth(N), facc(N) ----
    if (lane == 0) {
        const int N = NRAYS;
        float bgc = 1.0f - sa;
        out[3 * ray + 0] = sr + bgc;
        out[3 * ray + 1] = sg + bgc;
        out[3 * ray + 2] = sb + bgc;
        out[3 * N + ray] = sd;
        out[4 * N + ray] = sa;
        float fbgc = 1.0f - fsa;
        out[5 * N + 3 * ray + 0] = fsr + fbgc;
        out[5 * N + 3 * ray + 1] = fsg + fbgc;
        out[5 * N + 3 * ray + 2] = fsb + fbgc;
        out[8 * N + ray] = fsd;
        out[9 * N + ray] = fsa;
    }
}

extern "C" void kernel_launch(void* const* d_in, const int* in_sizes, int n_in,
                              void* d_out, int out_size) {
    const float* ro = nullptr;
    const float* rd = nullptr;
    const float* Wd = nullptr;
    const float* Wc = nullptr;
    for (int i = 0; i < n_in; i++) {
        int s = in_sizes[i];
        if (s == 3) Wd = (const float*)d_in[i];
        else if (s == 9) Wc = (const float*)d_in[i];
        else if (s == 3 * NRAYS) {
            if (!ro) ro = (const float*)d_in[i];
            else if (!rd) rd = (const float*)d_in[i];
        }
    }
    vr_kernel<<<NRAYS / WPB, 32 * WPB>>>(ro, rd, Wd, Wc, (float*)d_out);
}

// round 11
// speedup vs baseline: 2.6445x; 1.1069x over previous
#include <cuda_runtime.h>

#define NRAYS 131072
#define WPB 8            // warps (rays) per block
#define NS 64
#define NF 128

__device__ __forceinline__ float tanh_approx(float x) {
    float y;
    asm("tanh.approx.f32 %0, %1;" : "=f"(y) : "f"(x));
    return y;
}
// sigmoid(2*xh) = 0.5*tanh(xh)+0.5 ; caller passes the pre-halved logit
__device__ __forceinline__ float sigmoid_h(float xh) {
    return fmaf(0.5f, tanh_approx(xh), 0.5f);
}
__device__ __forceinline__ float ex2(float x) {
    float y;
    asm("ex2.approx.f32 %0, %1;" : "=f"(y) : "f"(x));
    return y;
}
// dens2 = softplus(x) * log2(e) = log2(1 + e^x), branchless (no warp divergence):
//   = log2e*max(x,0) + log2(1 + e^-|x|)
// small-y series has log2e folded into its coefficients; select, don't branch.
__device__ __forceinline__ float softplus_lg2(float x) {
    float y = __expf(-fabsf(x));
    // log2e * y * (1 - y/2 + y^2/3 - y^3/4)
    float ser = y * fmaf(y, fmaf(y, fmaf(-0.36067376f, y, 0.48089835f),
                                 -0.72134752f), 1.44269504f);
    float big = __log2f(1.0f + y);
    float l2 = (y < 0.03125f) ? ser : big;
    return fmaf(fmaxf(x, 0.0f), 1.44269504f, l2);
}
// coarse grid value, exact same floats as reference linspace
__device__ __forceinline__ float t_of_i(int i) {
    float x = (i == 63) ? 1.0f : (float)i * (1.0f / 63.0f);
    return fmaf(4.0f, x, 2.0f);
}
__device__ __forceinline__ float warp_red_sum(float x) {
#pragma unroll
    for (int d = 16; d > 0; d >>= 1) x += __shfl_xor_sync(0xffffffffu, x, d);
    return x;
}
__device__ __forceinline__ float warp_scan_prod(float x, int lane) {
#pragma unroll
    for (int d = 1; d < 32; d <<= 1) {
        float v = __shfl_up_sync(0xffffffffu, x, d);
        if (lane >= d) x *= v;
    }
    return x;
}
__device__ __forceinline__ float warp_scan_sum(float x, int lane) {
#pragma unroll
    for (int d = 1; d < 32; d <<= 1) {
        float v = __shfl_up_sync(0xffffffffu, x, d);
        if (lane >= d) x += v;
    }
    return x;
}

// count of c[i] <= u over exactly 64 sorted entries (result in [0,64])
__device__ __forceinline__ int cnt64_le(const float* c, float u) {
    if (c[63] <= u) return 64;
    int pos = 0;
#pragma unroll
    for (int step = 32; step >= 1; step >>= 1)
        if (c[pos + step - 1] <= u) pos += step;
    return pos;
}
// count of c[i] < v over exactly 64 sorted entries (result in [0,64])
__device__ __forceinline__ int cnt64_lt(const float* c, float v) {
    if (c[63] < v) return 64;
    int pos = 0;
#pragma unroll
    for (int step = 32; step >= 1; step >>= 1)
        if (c[pos + step - 1] < v) pos += step;
    return pos;
}
// count of {i in [0,64): t_of_i(i) <= v}  -- analytic guess + exact correction
__device__ __forceinline__ int cnt_ta_le(float v) {
    float g = fmaf(v, 15.75f, -31.5f);     // (v-2)*63/4
    int c = (int)floorf(g) + 1;
    c = min(64, max(0, c));
    if (c < 64 && t_of_i(c) <= v) c++;
    if (c < 64 && t_of_i(c) <= v) c++;
    if (c > 0 && t_of_i(c - 1) > v) c--;
    if (c > 0 && t_of_i(c - 1) > v) c--;
    return c;
}

__global__ void __launch_bounds__(32 * WPB, 7) vr_kernel(
    const float* __restrict__ ro, const float* __restrict__ rd,
    const float* __restrict__ Wd, const float* __restrict__ Wc,
    float* __restrict__ out)
{
    const int w = threadIdx.x >> 5;
    const int lane = threadIdx.x & 31;
    const int ray = blockIdx.x * WPB + w;

    __shared__ float s_ts[WPB][NS];              // importance samples
    __shared__ float s_cdf[WPB][NS + 1];         // normalized cdf
    __shared__ __align__(16) float s_ft[WPB][132]; // merged fine t (row 16B-aligned)

    float* ts = s_ts[w];
    float* cdf = s_cdf[w];
    float* ft = s_ft[w];

    // ---- per-ray precompute: pos @ W = (ro.W) + t*(rd.W) ----
    const float ox = ro[3 * ray + 0], oy = ro[3 * ray + 1], oz = ro[3 * ray + 2];
    const float dx = rd[3 * ray + 0], dy = rd[3 * ray + 1], dz = rd[3 * ray + 2];
    const float wd0 = __ldg(&Wd[0]), wd1 = __ldg(&Wd[1]), wd2 = __ldg(&Wd[2]);
    const float ad = ox * wd0 + oy * wd1 + oz * wd2;
    const float bd = dx * wd0 + dy * wd1 + dz * wd2;
    float ach[3], bch[3];   // PRE-HALVED color coefficients for tanh-sigmoid
#pragma unroll
    for (int k = 0; k < 3; k++) {
        float w0 = __ldg(&Wc[k]), w1 = __ldg(&Wc[3 + k]), w2 = __ldg(&Wc[6 + k]);
        ach[k] = 0.5f * (ox * w0 + oy * w1 + oz * w2);
        bch[k] = 0.5f * (dx * w0 + dy * w1 + dz * w2);
    }

    // ================= COARSE PASS (2 samples/lane) =================
    float t_c[2], al_c[2], f_c[2], cr_c[2], cg_c[2], cb_c[2];
#pragma unroll
    for (int c = 0; c < 2; c++) {
        int i = 2 * lane + c;
        float t = t_of_i(i);
        float dist = (i < 63) ? (t_of_i(i + 1) - t) : 1e10f;
        float dens2 = softplus_lg2(fmaf(t, bd, ad));     // softplus * log2e
        float a = 1.0f - ex2(-dens2 * dist);             // 1 - exp(-dens*dist)
        al_c[c] = a;
        f_c[c] = (1.0f - a) + 1e-10f;
        t_c[c] = t;
        cr_c[c] = sigmoid_h(fmaf(t, bch[0], ach[0]));
        cg_c[c] = sigmoid_h(fmaf(t, bch[1], ach[1]));
        cb_c[c] = sigmoid_h(fmaf(t, bch[2], ach[2]));
    }
    // exclusive product scan of transmittance factors over 64 (2 per lane)
    float P = f_c[0] * f_c[1];
    float S = warp_scan_prod(P, lane);
    float E = __shfl_up_sync(0xffffffffu, S, 1);
    if (lane == 0) E = 1.0f;

    float wgt0 = al_c[0] * E;
    float wgt1 = al_c[1] * (E * f_c[0]);

    float sr = wgt0 * cr_c[0] + wgt1 * cr_c[1];
    float sg = wgt0 * cg_c[0] + wgt1 * cg_c[1];
    float sb = wgt0 * cb_c[0] + wgt1 * cb_c[1];
    float sd = wgt0 * t_c[0] + wgt1 * t_c[1];
    float sa = wgt0 + wgt1;
    sr = warp_red_sum(sr); sg = warp_red_sum(sg); sb = warp_red_sum(sb);
    sd = warp_red_sum(sd); sa = warp_red_sum(sa);

    // ---- CDF ----
    float wp0 = wgt0 + 1e-5f;
    float wp1 = wgt1 + 1e-5f;
    float Ps = wp0 + wp1;
    float Ss = warp_scan_sum(Ps, lane);
    float Es = __shfl_up_sync(0xffffffffu, Ss, 1);
    if (lane == 0) Es = 0.0f;
    float total = __shfl_sync(0xffffffffu, Ss, 31);
    float inv_total = __fdividef(1.0f, total);
    if (lane == 0) cdf[0] = 0.0f;
    cdf[2 * lane + 1] = (Es + wp0) * inv_total;
    cdf[2 * lane + 2] = (Es + Ps) * inv_total;
    __syncwarp();

    // ---- inverse-CDF importance sampling (2 u's / lane), values kept in regs ----
    float tsv[2];
#pragma unroll
    for (int c = 0; c < 2; c++) {
        int k = 2 * lane + c;
        float u = (k == 63) ? 1.0f : (float)k * (1.0f / 63.0f);
        int idx = 1 + cnt64_le(cdf + 1, u);   // searchsorted 'right' over 65 entries
        int below = idx - 1;
        int above = (idx < 64) ? idx : 64;
        float cdf0 = cdf[below];
        float cdf1 = cdf[above];
        float bin0 = t_of_i((below < 63) ? below : 63);
        float bin1 = t_of_i((above < 63) ? above : 63);
        float denom = cdf1 - cdf0;
        if (denom < 1e-5f) denom = 1.0f;
        float tt = __fdividef(u - cdf0, denom);
        float v = fmaf(tt, bin1 - bin0, bin0);
        tsv[c] = v;
        ts[k] = v;
    }
    __syncwarp();

    // ---- merge ranks: A (coarse, analytic) + B (importance) -> scatter to ft ----
#pragma unroll
    for (int c = 0; c < 2; c++) {
        int j = 2 * lane + c;
        float av = t_c[c];
        ft[j + cnt64_lt(ts, av)] = av;      // a before equal b
        float bv = tsv[c];
        ft[j + cnt_ta_le(bv)] = bv;
    }
    __syncwarp();

    // ================= FINE PASS (4 samples/lane, vectorized load) =================
    const float4 q = *reinterpret_cast<const float4*>(&ft[4 * lane]);
    const float t5 = ft[4 * lane + 4];       // lane 31: unused garbage (guarded)
    float tf[5] = {q.x, q.y, q.z, q.w, t5};

    float al[4], ff[4], fr[4], fg[4], fb[4];
#pragma unroll
    for (int c = 0; c < 4; c++) {
        int i = 4 * lane + c;
        float t = tf[c];
        float dist = (i < 127) ? (tf[c + 1] - t) : 1e10f;
        float dens2 = softplus_lg2(fmaf(t, bd, ad));
        float a = 1.0f - ex2(-dens2 * dist);
        al[c] = a;
        ff[c] = (1.0f - a) + 1e-10f;
        fr[c] = sigmoid_h(fmaf(t, bch[0], ach[0]));
        fg[c] = sigmoid_h(fmaf(t, bch[1], ach[1]));
        fb[c] = sigmoid_h(fmaf(t, bch[2], ach[2]));
    }
    float Pf = (ff[0] * ff[1]) * (ff[2] * ff[3]);
    float Sf = warp_scan_prod(Pf, lane);
    float Ef = __shfl_up_sync(0xffffffffu, Sf, 1);
    if (lane == 0) Ef = 1.0f;

    float fsr = 0.f, fsg = 0.f, fsb = 0.f, fsd = 0.f, fsa = 0.f;
    float trans = Ef;
#pragma unroll
    for (int c = 0; c < 4; c++) {
        float wgt = al[c] * trans;
        fsr += wgt * fr[c];
        fsg += wgt * fg[c];
        fsb += wgt * fb[c];
        fsd += wgt * tf[c];
        fsa += wgt;
        trans *= ff[c];
    }
    fsr = warp_red_sum(fsr); fsg = warp_red_sum(fsg); fsb = warp_red_sum(fsb);
    fsd = warp_red_sum(fsd); fsa = warp_red_sum(fsa);

    // ---- outputs: rgb(3N), depth(N), acc(N), frgb(3N), fdepth(N), facc(N) ----
    if (lane == 0) {
        const int N = NRAYS;
        float bgc = 1.0f - sa;
        out[3 * ray + 0] = sr + bgc;
        out[3 * ray + 1] = sg + bgc;
        out[3 * ray + 2] = sb + bgc;
        out[3 * N + ray] = sd;
        out[4 * N + ray] = sa;
        float fbgc = 1.0f - fsa;
        out[5 * N + 3 * ray + 0] = fsr + fbgc;
        out[5 * N + 3 * ray + 1] = fsg + fbgc;
        out[5 * N + 3 * ray + 2] = fsb + fbgc;
        out[8 * N + ray] = fsd;
        out[9 * N + ray] = fsa;
    }
}

extern "C" void kernel_launch(void* const* d_in, const int* in_sizes, int n_in,
                              void* d_out, int out_size) {
    const float* ro = nullptr;
    const float* rd = nullptr;
    const float* Wd = nullptr;
    const float* Wc = nullptr;
    for (int i = 0; i < n_in; i++) {
        int s = in_sizes[i];
        if (s == 3) Wd = (const float*)d_in[i];
        else if (s == 9) Wc = (const float*)d_in[i];
        else if (s == 3 * NRAYS) {
            if (!ro) ro = (const float*)d_in[i];
            else if (!rd) rd = (const float*)d_in[i];
        }
    }
    vr_kernel<<<NRAYS / WPB, 32 * WPB>>>(ro, rd, Wd, Wc, (float*)d_out);
}

// round 12
// speedup vs baseline: 3.1208x; 1.1801x over previous
#include <cuda_runtime.h>

#define NRAYS 131072
#define RPB 16           // rays per block (2 per warp, 16-lane segments)
#define FULL 0xffffffffu

__device__ __forceinline__ float tanh_approx(float x) {
    float y;
    asm("tanh.approx.f32 %0, %1;" : "=f"(y) : "f"(x));
    return y;
}
// sigmoid(2*xh) = 0.5*tanh(xh)+0.5 ; caller passes the pre-halved logit
__device__ __forceinline__ float sigmoid_h(float xh) {
    return fmaf(0.5f, tanh_approx(xh), 0.5f);
}
__device__ __forceinline__ float ex2(float x) {
    float y;
    asm("ex2.approx.f32 %0, %1;" : "=f"(y) : "f"(x));
    return y;
}
// dens2 = softplus(x)*log2e = log2(1+e^x), branchless select (no divergence)
__device__ __forceinline__ float softplus_lg2(float x) {
    float y = __expf(-fabsf(x));
    float ser = y * fmaf(y, fmaf(y, fmaf(-0.36067376f, y, 0.48089835f),
                                 -0.72134752f), 1.44269504f);
    float big = __log2f(1.0f + y);
    float l2 = (y < 0.03125f) ? ser : big;
    return fmaf(fmaxf(x, 0.0f), 1.44269504f, l2);
}
// coarse grid value, exact same floats as reference linspace
__device__ __forceinline__ float t_of_i(int i) {
    float x = (i == 63) ? 1.0f : (float)i * (1.0f / 63.0f);
    return fmaf(4.0f, x, 2.0f);
}

// count of c[i] <= u over exactly 64 sorted entries (result in [0,64])
__device__ __forceinline__ int cnt64_le(const float* c, float u) {
    if (c[63] <= u) return 64;
    int pos = 0;
#pragma unroll
    for (int step = 32; step >= 1; step >>= 1)
        if (c[pos + step - 1] <= u) pos += step;
    return pos;
}
// count of c[i] < v over exactly 64 sorted entries (result in [0,64])
__device__ __forceinline__ int cnt64_lt(const float* c, float v) {
    if (c[63] < v) return 64;
    int pos = 0;
#pragma unroll
    for (int step = 32; step >= 1; step >>= 1)
        if (c[pos + step - 1] < v) pos += step;
    return pos;
}
// count of {i in [0,64): t_of_i(i) <= v}  -- analytic guess + exact correction
__device__ __forceinline__ int cnt_ta_le(float v) {
    float g = fmaf(v, 15.75f, -31.5f);     // (v-2)*63/4
    int c = (int)floorf(g) + 1;
    c = min(64, max(0, c));
    if (c < 64 && t_of_i(c) <= v) c++;
    if (c < 64 && t_of_i(c) <= v) c++;
    if (c > 0 && t_of_i(c - 1) > v) c--;
    if (c > 0 && t_of_i(c - 1) > v) c--;
    return c;
}
// reduce-sum within a 16-lane segment (xor d<16 never crosses segments)
__device__ __forceinline__ float seg_red_sum(float x) {
#pragma unroll
    for (int d = 8; d >= 1; d >>= 1) x += __shfl_xor_sync(FULL, x, d);
    return x;
}

__global__ void __launch_bounds__(256, 6) vr_kernel(
    const float* __restrict__ ro, const float* __restrict__ rd,
    const float* __restrict__ Wd, const float* __restrict__ Wc,
    float* __restrict__ out)
{
    const int tid = threadIdx.x;
    const int s = tid & 15;              // sub-lane within segment
    const int seg = tid >> 4;            // segment (ray) index within block
    const int ray = blockIdx.x * RPB + seg;

    __shared__ float s_ts[RPB][64];
    __shared__ float s_cdf[RPB][65];
    __shared__ __align__(16) float s_ft[RPB][132];

    float* ts = s_ts[seg];
    float* cdf = s_cdf[seg];
    float* ft = s_ft[seg];

    // ---- per-ray precompute: pos @ W = (ro.W) + t*(rd.W) ----
    const float ox = ro[3 * ray + 0], oy = ro[3 * ray + 1], oz = ro[3 * ray + 2];
    const float dx = rd[3 * ray + 0], dy = rd[3 * ray + 1], dz = rd[3 * ray + 2];
    const float wd0 = __ldg(&Wd[0]), wd1 = __ldg(&Wd[1]), wd2 = __ldg(&Wd[2]);
    const float ad = ox * wd0 + oy * wd1 + oz * wd2;
    const float bd = dx * wd0 + dy * wd1 + dz * wd2;
    float ach[3], bch[3];   // PRE-HALVED color coefficients for tanh-sigmoid
#pragma unroll
    for (int k = 0; k < 3; k++) {
        float w0 = __ldg(&Wc[k]), w1 = __ldg(&Wc[3 + k]), w2 = __ldg(&Wc[6 + k]);
        ach[k] = 0.5f * (ox * w0 + oy * w1 + oz * w2);
        bch[k] = 0.5f * (dx * w0 + dy * w1 + dz * w2);
    }

    // ========= COARSE PASS: 4 samples/lane, local-accumulate =========
    float t_c[4], localw[4];
    float trans_l = 1.0f;
    float lsr = 0.f, lsg = 0.f, lsb = 0.f, lsd = 0.f, lsa = 0.f;
#pragma unroll
    for (int c = 0; c < 4; c++) {
        int i = 4 * s + c;
        float t = t_of_i(i);
        t_c[c] = t;
        float dist = (i < 63) ? (t_of_i(i + 1) - t) : 1e10f;
        float dens2 = softplus_lg2(fmaf(t, bd, ad));
        float a = 1.0f - ex2(-dens2 * dist);
        float f = (1.0f - a) + 1e-10f;
        float wl = a * trans_l;
        localw[c] = wl;
        float cr = sigmoid_h(fmaf(t, bch[0], ach[0]));
        float cg = sigmoid_h(fmaf(t, bch[1], ach[1]));
        float cb = sigmoid_h(fmaf(t, bch[2], ach[2]));
        lsr += wl * cr; lsg += wl * cg; lsb += wl * cb;
        lsd += wl * t;  lsa += wl;
        trans_l *= f;
    }
    // segmented exclusive product scan of per-lane transmittance
    float S = trans_l;
#pragma unroll
    for (int d = 1; d < 16; d <<= 1) {
        float v = __shfl_up_sync(FULL, S, d, 16);
        if (s >= d) S *= v;
    }
    float E = __shfl_up_sync(FULL, S, 1, 16);
    if (s == 0) E = 1.0f;

    float sr = E * lsr, sg = E * lsg, sb = E * lsb, sd = E * lsd, sa = E * lsa;
    sr = seg_red_sum(sr); sg = seg_red_sum(sg); sb = seg_red_sum(sb);
    sd = seg_red_sum(sd); sa = seg_red_sum(sa);

    // ---- CDF ----
    float ps0 = E * localw[0] + 1e-5f;
    float ps1 = ps0 + (E * localw[1] + 1e-5f);
    float ps2 = ps1 + (E * localw[2] + 1e-5f);
    float ps3 = ps2 + (E * localw[3] + 1e-5f);
    float Ss = ps3;
#pragma unroll
    for (int d = 1; d < 16; d <<= 1) {
        float v = __shfl_up_sync(FULL, Ss, d, 16);
        if (s >= d) Ss += v;
    }
    float Es = __shfl_up_sync(FULL, Ss, 1, 16);
    if (s == 0) Es = 0.0f;
    float total = __shfl_sync(FULL, Ss, 15, 16);
    float inv_total = __fdividef(1.0f, total);
    if (s == 0) cdf[0] = 0.0f;
    cdf[4 * s + 1] = (Es + ps0) * inv_total;
    cdf[4 * s + 2] = (Es + ps1) * inv_total;
    cdf[4 * s + 3] = (Es + ps2) * inv_total;
    cdf[4 * s + 4] = (Es + ps3) * inv_total;
    __syncwarp();

    // ---- inverse-CDF importance sampling (4 u's / lane) ----
    float tsv[4];
#pragma unroll
    for (int c = 0; c < 4; c++) {
        int k = 4 * s + c;
        float u = (k == 63) ? 1.0f : (float)k * (1.0f / 63.0f);
        int idx = 1 + cnt64_le(cdf + 1, u);   // searchsorted 'right' over 65 entries
        int below = idx - 1;
        int above = (idx < 64) ? idx : 64;
        float cdf0 = cdf[below];
        float cdf1 = cdf[above];
        float bin0 = t_of_i((below < 63) ? below : 63);
        float bin1 = t_of_i((above < 63) ? above : 63);
        float denom = cdf1 - cdf0;
        if (denom < 1e-5f) denom = 1.0f;
        float tt = __fdividef(u - cdf0, denom);
        float v = fmaf(tt, bin1 - bin0, bin0);
        tsv[c] = v;
        ts[k] = v;
    }
    __syncwarp();

    // ---- merge ranks -> scatter to ft ----
#pragma unroll
    for (int c = 0; c < 4; c++) {
        int j = 4 * s + c;
        float av = t_c[c];
        ft[j + cnt64_lt(ts, av)] = av;      // a before equal b
        float bv = tsv[c];
        ft[j + cnt_ta_le(bv)] = bv;
    }
    __syncwarp();

    // ========= FINE PASS: 8 samples/lane, local-accumulate =========
    const float4 q1 = *reinterpret_cast<const float4*>(&ft[8 * s]);
    const float4 q2 = *reinterpret_cast<const float4*>(&ft[8 * s + 4]);
    const float t9 = ft[8 * s + 8];   // s==15: garbage, guarded by i<127
    float tf[9] = {q1.x, q1.y, q1.z, q1.w, q2.x, q2.y, q2.z, q2.w, t9};

    float ltr = 1.0f;
    float lfr = 0.f, lfg = 0.f, lfb = 0.f, lfd = 0.f, lfa = 0.f;
#pragma unroll
    for (int c = 0; c < 8; c++) {
        int i = 8 * s + c;
        float t = tf[c];
        float dist = (i < 127) ? (tf[c + 1] - t) : 1e10f;
        float dens2 = softplus_lg2(fmaf(t, bd, ad));
        float a = 1.0f - ex2(-dens2 * dist);
        float f = (1.0f - a) + 1e-10f;
        float wl = a * ltr;
        float cr = sigmoid_h(fmaf(t, bch[0], ach[0]));
        float cg = sigmoid_h(fmaf(t, bch[1], ach[1]));
        float cb = sigmoid_h(fmaf(t, bch[2], ach[2]));
        lfr += wl * cr; lfg += wl * cg; lfb += wl * cb;
        lfd += wl * t;  lfa += wl;
        ltr *= f;
    }
    float Sf = ltr;
#pragma unroll
    for (int d = 1; d < 16; d <<= 1) {
        float v = __shfl_up_sync(FULL, Sf, d, 16);
        if (s >= d) Sf *= v;
    }
    float Ef = __shfl_up_sync(FULL, Sf, 1, 16);
    if (s == 0) Ef = 1.0f;

    float fsr = Ef * lfr, fsg = Ef * lfg, fsb = Ef * lfb;
    float fsd = Ef * lfd, fsa = Ef * lfa;
    fsr = seg_red_sum(fsr); fsg = seg_red_sum(fsg); fsb = seg_red_sum(fsb);
    fsd = seg_red_sum(fsd); fsa = seg_red_sum(fsa);

    // ---- outputs: rgb(3N), depth(N), acc(N), frgb(3N), fdepth(N), facc(N) ----
    if (s == 0) {
        const int N = NRAYS;
        float bgc = 1.0f - sa;
        out[3 * ray + 0] = sr + bgc;
        out[3 * ray + 1] = sg + bgc;
        out[3 * ray + 2] = sb + bgc;
        out[3 * N + ray] = sd;
        out[4 * N + ray] = sa;
        float fbgc = 1.0f - fsa;
        out[5 * N + 3 * ray + 0] = fsr + fbgc;
        out[5 * N + 3 * ray + 1] = fsg + fbgc;
        out[5 * N + 3 * ray + 2] = fsb + fbgc;
        out[8 * N + ray] = fsd;
        out[9 * N + ray] = fsa;
    }
}

extern "C" void kernel_launch(void* const* d_in, const int* in_sizes, int n_in,
                              void* d_out, int out_size) {
    const float* ro = nullptr;
    const float* rd = nullptr;
    const float* Wd = nullptr;
    const float* Wc = nullptr;
    for (int i = 0; i < n_in; i++) {
        int sz = in_sizes[i];
        if (sz == 3) Wd = (const float*)d_in[i];
        else if (sz == 9) Wc = (const float*)d_in[i];
        else if (sz == 3 * NRAYS) {
            if (!ro) ro = (const float*)d_in[i];
            else if (!rd) rd = (const float*)d_in[i];
        }
    }
    vr_kernel<<<NRAYS / RPB, 256>>>(ro, rd, Wd, Wc, (float*)d_out);
}